// round 8
// baseline (speedup 1.0000x reference)
#include <cuda_runtime.h>
#include <cuda_bf16.h>
#include <cuda_fp16.h>
#include <math.h>
#include <stdint.h>

#define NB 4
#define NN 50000
#define NT (NB*NN)
#define H4 128
#define RF 64
#define CH 98
#define CHSZ 512

#define ALPHA 0.4204482076268573f   /* 32^-0.25 */
#define RATIO 0.125f                /* 1/sqrt(64) */
#define EPSRF 1e-6f
#define EPSLN 1e-5f

/* ------------------------------ scratch ------------------------------ */
__device__ float  g_h0[(size_t)NT*H4];
__device__ float  g_h [(size_t)NT*H4];
__device__ __half g_vh[(size_t)NT*H4];
__device__ float  g_q [(size_t)NT*RF];
__device__ float  g_dash2[(size_t)NT*RF];
__device__ float  g_diag2[NT];
__device__ __half g_kh[(size_t)NT*RF];
__device__ int    g_mx[NB];
__device__ float  g_part [(size_t)NB*CH*RF*H4];
__device__ float  g_kpart[(size_t)NB*CH*RF];
__device__ float  g_v2x[(size_t)NB*RF*H4];
__device__ float  g_ksum[NB*RF];

/* ------------------------------ helpers ------------------------------ */
__device__ __forceinline__ float warpSum(float v){
    #pragma unroll
    for (int o=16;o;o>>=1) v += __shfl_xor_sync(0xffffffffu, v, o);
    return v;
}
__device__ __forceinline__ float warpMax(float v){
    #pragma unroll
    for (int o=16;o;o>>=1) v = fmaxf(v, __shfl_xor_sync(0xffffffffu, v, o));
    return v;
}
__device__ __forceinline__ int f2ord(float f){
    int i = __float_as_int(f);
    return (i >= 0) ? i : (i ^ 0x7FFFFFFF);
}
__device__ __forceinline__ float ord2f(int i){
    return __int_as_float((i >= 0) ? i : (i ^ 0x7FFFFFFF));
}

/* --------------------- mma.sync helpers (base sm_100 ISA) ------------ */
__device__ __forceinline__ uint32_t smem_u32(const void* p){
    uint32_t a;
    asm("{ .reg .u64 t; cvta.to.shared.u64 t, %1; cvt.u32.u64 %0, t; }"
        : "=r"(a) : "l"(p));
    return a;
}
__device__ __forceinline__ void ldsm_x4(uint32_t* r, uint32_t addr){
    asm volatile("ldmatrix.sync.aligned.m8n8.x4.shared.b16 {%0,%1,%2,%3}, [%4];"
        : "=r"(r[0]), "=r"(r[1]), "=r"(r[2]), "=r"(r[3]) : "r"(addr));
}
__device__ __forceinline__ void mma16816h(float* d, const uint32_t* a, const uint32_t* b){
    asm volatile("mma.sync.aligned.m16n8k16.row.col.f32.f16.f16.f32 "
        "{%0,%1,%2,%3}, {%4,%5,%6,%7}, {%8,%9}, {%0,%1,%2,%3};"
        : "+f"(d[0]), "+f"(d[1]), "+f"(d[2]), "+f"(d[3])
        : "r"(a[0]), "r"(a[1]), "r"(a[2]), "r"(a[3]), "r"(b[0]), "r"(b[1]));
}
__device__ __forceinline__ uint4 pack8_f16(const float* src){
    float4 a = ((const float4*)src)[0];
    float4 b = ((const float4*)src)[1];
    __half2 p0 = __floats2half2_rn(a.x, a.y);
    __half2 p1 = __floats2half2_rn(a.z, a.w);
    __half2 p2 = __floats2half2_rn(b.x, b.y);
    __half2 p3 = __floats2half2_rn(b.z, b.w);
    uint4 w;
    w.x = *reinterpret_cast<uint32_t*>(&p0);
    w.y = *reinterpret_cast<uint32_t*>(&p1);
    w.z = *reinterpret_cast<uint32_t*>(&p2);
    w.w = *reinterpret_cast<uint32_t*>(&p3);
    return w;
}

/* ------------------------------ init --------------------------------- */
__global__ void initmx_k(){
    if (threadIdx.x < NB) g_mx[threadIdx.x] = (int)0x80000000;
}

/* --------------------------- phase 1 --------------------------------- */
__global__ void phase1_k(const float* __restrict__ x,
                         const float* __restrict__ node_emb,
                         const float* __restrict__ time_emb,
                         const float* __restrict__ week_emb,
                         const float* __restrict__ Win, const float* __restrict__ bin,
                         const float* __restrict__ W1,  const float* __restrict__ b1,
                         const float* __restrict__ W2,  const float* __restrict__ b2,
                         const float* __restrict__ proj)
{
    __shared__ float sWinT[36*32];
    __shared__ float sW1T[96*32];
    __shared__ float sW2T[96*32];
    __shared__ float sprojT[32*64];
    __shared__ float sbin[32], sb1[32], sb2[32];
    __shared__ float swp[8][176];
    __shared__ int   sbmax[NB];

    int tid = threadIdx.x;
    for (int t=tid; t<32*36; t+=256){ int h=t/36, j=t%36; sWinT[j*32+h]=Win[t]; }
    for (int t=tid; t<32*96; t+=256){ int h=t/96, j=t%96; sW1T[j*32+h]=W1[t]; sW2T[j*32+h]=W2[t]; }
    for (int t=tid; t<64*32; t+=256){ int m=t/32, d=t%32; sprojT[d*64+m]=proj[t]; }
    if (tid<32){ sbin[tid]=bin[tid]; sb1[tid]=b1[tid]; sb2[tid]=b2[tid]; }
    if (tid<NB) sbmax[tid] = (int)0x80000000;
    __syncthreads();

    int w = tid>>5, l = tid&31;
    float* xv = swp[w];
    float* xg = swp[w]+40;
    float* nv = swp[w]+136;

    float wmax = -1e30f;

    #pragma unroll 1
    for (int it=0; it<8; it++){
        int i = (blockIdx.x*8 + w)*8 + it;
        int b = i / NN;
        int n = i - b*NN;

        const float* xr = x + (size_t)i*36;
        xv[l] = xr[l];
        if (l < 4) xv[32+l] = xr[32+l];
        __syncwarp();

        int ti = (int)(xv[34]*288.0f); ti = min(max(ti,0),287);
        int wk = (int)(xv[35]);        wk = min(max(wk,0),6);

        float ne = node_emb[n*32+l];
        float te = time_emb[ti*32+l];
        float we = week_emb[wk*32+l];

        float inp = sbin[l];
        #pragma unroll
        for (int j=0;j<36;j++) inp = fmaf(sWinT[j*32+l], xv[j], inp);

        size_t hb = (size_t)i*128;
        g_h0[hb+l]=inp; g_h0[hb+32+l]=ne; g_h0[hb+64+l]=te; g_h0[hb+96+l]=we;

        xg[l]=ne; xg[32+l]=te; xg[64+l]=we;
        __syncwarp();

        float a1 = sb1[l];
        #pragma unroll
        for (int j=0;j<96;j++) a1 = fmaf(sW1T[j*32+l], xg[j], a1);
        a1 *= ALPHA;
        nv[l] = a1; __syncwarp();
        float diag1 = 0.5f * warpSum(a1*a1);
        float d0=0.f, d1=0.f;
        #pragma unroll
        for (int dd=0; dd<32; dd++){
            float f = nv[dd];
            d0 = fmaf(f, sprojT[dd*64+l],    d0);
            d1 = fmaf(f, sprojT[dd*64+32+l], d1);
        }
        float mx1 = warpMax(fmaxf(d0,d1));
        g_q[(size_t)i*64 + l]      = RATIO*(expf(d0 - diag1 - mx1) + EPSRF);
        g_q[(size_t)i*64 + 32 + l] = RATIO*(expf(d1 - diag1 - mx1) + EPSRF);
        __syncwarp();

        float a2 = sb2[l];
        #pragma unroll
        for (int j=0;j<96;j++) a2 = fmaf(sW2T[j*32+l], xg[j], a2);
        a2 *= ALPHA;
        nv[l] = a2; __syncwarp();
        float diag2 = 0.5f * warpSum(a2*a2);
        d0=0.f; d1=0.f;
        #pragma unroll
        for (int dd=0; dd<32; dd++){
            float f = nv[dd];
            d0 = fmaf(f, sprojT[dd*64+l],    d0);
            d1 = fmaf(f, sprojT[dd*64+32+l], d1);
        }
        g_dash2[(size_t)i*64 + l]      = d0;
        g_dash2[(size_t)i*64 + 32 + l] = d1;
        if (l==0) g_diag2[i] = diag2;
        wmax = fmaxf(wmax, fmaxf(d0,d1));
        __syncwarp();
    }

    {
        int i0 = (blockIdx.x*8 + w)*8;
        int b = i0 / NN;
        float m = warpMax(wmax);
        if (l==0) atomicMax(&sbmax[b], f2ord(m));
    }

    __syncthreads();
    if (tid < NB && sbmax[tid] != (int)0x80000000)
        atomicMax(&g_mx[tid], sbmax[tid]);
}

/* --------------------------- k features (fp16 out) ------------------- */
__global__ void computek_k(){
    int idx = blockIdx.x*256 + threadIdx.x;
    int i = idx >> 6;
    int b = i / NN;
    float mx = ord2f(g_mx[b]);
    float val = RATIO*(expf(g_dash2[idx] - g_diag2[i] - mx) + EPSRF);
    g_kh[idx] = __float2half(val);
}

/* ------------------- ksum partial + final (hoisted) ------------------ */
__global__ void ksump_k(){
    __shared__ float red[4][64];
    int b = blockIdx.y, ch = blockIdx.x;
    int tid = threadIdx.x;
    int m = tid & 63, part = tid >> 6;
    float s = 0.f;
    int nb = ch*CHSZ + part*128;
    #pragma unroll 4
    for (int nn=0; nn<128; nn++){
        int n = nb + nn;
        if (n < NN) s += __half2float(g_kh[((size_t)(b*NN+n))*64 + m]);
    }
    red[part][m] = s;
    __syncthreads();
    if (part == 0){
        float t = red[0][m] + red[1][m] + red[2][m] + red[3][m];
        g_kpart[(size_t)(b*CH+ch)*64 + m] = t;
    }
}

__global__ void ksumr_k(){
    int tid = threadIdx.x;
    int b = tid >> 6, m = tid & 63;
    float s = 0.f;
    for (int ch=0; ch<CH; ch++)
        s += g_kpart[(size_t)(b*CH+ch)*64 + m];
    g_ksum[b*64 + m] = s;
}

/* ------------------------- GLU via mma.sync (fp16) ------------------- */
#define GT_TILES ((NT + 255)/256)
#define G3_SA   0
#define G3_SB   65536
#define G3_SBI  131072
#define G3_SBO  131584
#define G3_TOT  132096

extern __shared__ char gsm2[];

__global__ void __launch_bounds__(512,1)
glu3_k(const float* __restrict__ hin,
       const float* __restrict__ wi, const float* __restrict__ bi,
       const float* __restrict__ wo, const float* __restrict__ bo)
{
    char* SA = gsm2 + G3_SA;
    char* SB = gsm2 + G3_SB;
    float* sbi = (float*)(gsm2 + G3_SBI);
    float* sbo = (float*)(gsm2 + G3_SBO);
    int tid = threadIdx.x;

    /* stage W = [wi(128); wo(128)] as fp16, swizzled 16B chunks */
    for (int c = tid; c < 4096; c += 512){
        int n = c >> 4, ch = c & 15;
        const float* src = (n < 128) ? (wi + (size_t)n*128 + ch*8)
                                     : (wo + (size_t)(n-128)*128 + ch*8);
        *reinterpret_cast<uint4*>(SB + n*256 + ((ch ^ (n&7))<<4)) = pack8_f16(src);
    }
    if (tid < 128){ sbi[tid] = bi[tid]; sbo[tid] = bo[tid]; }

    int w = tid>>5, l = tid&31;
    uint32_t saB = smem_u32(SA);
    uint32_t sbB = smem_u32(SB);

    int a_row = (w<<4) + (l & 15);
    int er    = (w<<4) + (l>>2);

    for (int tile = blockIdx.x; tile < GT_TILES; tile += gridDim.x){
        int base = tile << 8;

        for (int c = tid; c < 4096; c += 512){
            int r = c >> 4, ch = c & 15;
            uint4 pw = make_uint4(0,0,0,0);
            if (base + r < NT)
                pw = pack8_f16(hin + (size_t)(base + r)*128 + ch*8);
            *reinterpret_cast<uint4*>(SA + r*256 + ((ch ^ (r&7))<<4)) = pw;
        }
        __syncthreads();

        uint32_t Af[8][4];
        #pragma unroll
        for (int ks=0; ks<8; ks++){
            int kc = (ks<<1) + (l>>4);
            ldsm_x4(Af[ks], saB + a_row*256 + ((kc ^ (a_row&7))<<4));
        }

        #pragma unroll 1
        for (int nb=0; nb<16; nb++){
            int nrI = (nb<<3) + (l&7);
            int nrO = nrI + 128;
            uint32_t BI[16], BO[16];
            #pragma unroll
            for (int j=0;j<4;j++){
                int kc = (j<<2) + (l>>3);
                ldsm_x4(&BI[j<<2], sbB + nrI*256 + ((kc ^ (nrI&7))<<4));
                ldsm_x4(&BO[j<<2], sbB + nrO*256 + ((kc ^ (nrO&7))<<4));
            }
            float dI[4] = {0.f,0.f,0.f,0.f};
            float dO[4] = {0.f,0.f,0.f,0.f};
            #pragma unroll
            for (int ks=0; ks<8; ks++){
                mma16816h(dI, Af[ks], &BI[ks<<1]);
                mma16816h(dO, Af[ks], &BO[ks<<1]);
            }

            int c0 = (nb<<3) + ((l&3)<<1);
            float bi0 = sbi[c0], bi1 = sbi[c0+1];
            float bo0 = sbo[c0], bo1 = sbo[c0+1];
            int n0 = base + er;
            int n1 = n0 + 8;
            if (n0 < NT){
                float aI0 = dI[0] + bi0, aI1 = dI[1] + bi1;
                float ox = (dO[0] + bo0) / (1.f + expf(-aI0));
                float oy = (dO[1] + bo1) / (1.f + expf(-aI1));
                *reinterpret_cast<__half2*>(g_vh + (size_t)n0*128 + c0) = __floats2half2_rn(ox, oy);
            }
            if (n1 < NT){
                float aI2 = dI[2] + bi0, aI3 = dI[3] + bi1;
                float ox = (dO[2] + bo0) / (1.f + expf(-aI2));
                float oy = (dO[3] + bo1) / (1.f + expf(-aI3));
                *reinterpret_cast<__half2*>(g_vh + (size_t)n1*128 + c0) = __floats2half2_rn(ox, oy);
            }
        }
        __syncthreads();
    }
}

/* --------------- K^T V partials via mma.sync (deterministic) ---------
 * Per block (ch,b): acc[64 rf x 128 hd] over 512 nodes.  k,v staged
 * TRANSPOSED into 16B-ALIGNED padded smem so the verified no-trans
 * ldsm patterns apply: A = kT [rf][node], B = vT [hd][node].
 */
#define KT_PAD 40     /* halfs per row (32 data + 8 pad); 80 B rows, mult of 16 */
__global__ void __launch_bounds__(256,1)
kvredmma_k(){
    __shared__ __align__(16) __half SKt[64*KT_PAD];
    __shared__ __align__(16) __half SVt[128*KT_PAD];
    int b = blockIdx.y, ch = blockIdx.x;
    int tid = threadIdx.x, w = tid>>5, l = tid&31;
    uint32_t skB = smem_u32(SKt), svB = smem_u32(SVt);

    float acc[4][2][4];
    #pragma unroll
    for (int mt=0;mt<4;mt++)
        #pragma unroll
        for (int nb=0;nb<2;nb++)
            #pragma unroll
            for (int r=0;r<4;r++) acc[mt][nb][r] = 0.f;

    int nb0 = ch*CHSZ;
    #pragma unroll 1
    for (int c0=0; c0<CHSZ; c0+=32){
        int nbase = nb0 + c0;
        /* stage kT: thread: node tid&31, rf group tid>>5 (8 rf) */
        {
            int node = tid & 31, rg = tid >> 5;
            int n = nbase + node;
            if (n < NN){
                const __half2* s2 = (const __half2*)(g_kh + ((size_t)(b*NN+n))*64 + rg*8);
                #pragma unroll
                for (int j=0;j<4;j++){
                    __half2 p = s2[j];
                    SKt[(rg*8 + 2*j  )*KT_PAD + node] = __low2half(p);
                    SKt[(rg*8 + 2*j+1)*KT_PAD + node] = __high2half(p);
                }
            } else {
                #pragma unroll
                for (int j=0;j<4;j++){
                    SKt[(rg*8 + 2*j  )*KT_PAD + node] = __float2half(0.f);
                    SKt[(rg*8 + 2*j+1)*KT_PAD + node] = __float2half(0.f);
                }
            }
        }
        /* stage vT: thread: node tid&31, hd group tid>>5 (16 hd) */
        {
            int node = tid & 31, hg = tid >> 5;
            int n = nbase + node;
            if (n < NN){
                const __half2* s2 = (const __half2*)(g_vh + ((size_t)(b*NN+n))*128 + hg*16);
                #pragma unroll
                for (int j=0;j<8;j++){
                    __half2 p = s2[j];
                    SVt[(hg*16 + 2*j  )*KT_PAD + node] = __low2half(p);
                    SVt[(hg*16 + 2*j+1)*KT_PAD + node] = __high2half(p);
                }
            } else {
                #pragma unroll
                for (int j=0;j<8;j++){
                    SVt[(hg*16 + 2*j  )*KT_PAD + node] = __float2half(0.f);
                    SVt[(hg*16 + 2*j+1)*KT_PAD + node] = __float2half(0.f);
                }
            }
        }
        __syncthreads();

        /* B: warp w covers hd [w*16, +16) = 2 n8 blocks, k32 at once */
        uint32_t Bv[2][4];
        #pragma unroll
        for (int nb=0;nb<2;nb++){
            int row = w*16 + nb*8 + (l&7);
            ldsm_x4(Bv[nb], svB + row*(KT_PAD*2) + ((l>>3)<<4));
        }
        #pragma unroll
        for (int ks=0; ks<2; ks++){
            uint32_t Af[4][4];
            #pragma unroll
            for (int mt=0;mt<4;mt++){
                int row = mt*16 + (l&15);
                ldsm_x4(Af[mt], skB + row*(KT_PAD*2) + (((ks<<1) + (l>>4))<<4));
            }
            #pragma unroll
            for (int mt=0;mt<4;mt++){
                mma16816h(acc[mt][0], Af[mt], &Bv[0][ks<<1]);
                mma16816h(acc[mt][1], Af[mt], &Bv[1][ks<<1]);
            }
        }
        __syncthreads();
    }

    size_t pb = (size_t)(b*CH+ch);
    #pragma unroll
    for (int mt=0;mt<4;mt++){
        #pragma unroll
        for (int nb=0;nb<2;nb++){
            int rf0 = mt*16 + (l>>2);
            int hd = w*16 + nb*8 + 2*(l&3);
            float2 v0 = make_float2(acc[mt][nb][0], acc[mt][nb][1]);
            float2 v1 = make_float2(acc[mt][nb][2], acc[mt][nb][3]);
            *reinterpret_cast<float2*>(&g_part[(pb*64 + rf0    )*128 + hd]) = v0;
            *reinterpret_cast<float2*>(&g_part[(pb*64 + rf0 + 8)*128 + hd]) = v1;
        }
    }
}

__global__ void vred_k(){
    int idx = blockIdx.x*256 + threadIdx.x;
    int b = idx >> 13;
    int rem = idx & 8191;
    int m = rem >> 7, d = rem & 127;
    float s = 0.f;
    for (int ch=0; ch<CH; ch++)
        s += g_part[((size_t)(b*CH+ch)*64 + m)*128 + d];
    g_v2x[((size_t)b*64 + m)*128 + d] = s;
}

/* ------------- attention out + residual + layernorm ------------------ */
__global__ void attn_k(const float* __restrict__ res_in,
                       const float* __restrict__ lg, const float* __restrict__ lb){
    __shared__ float sv2x[64*128];
    __shared__ float sks[64];
    __shared__ float sg[128], sb[128];

    int b = blockIdx.y;
    int tid = threadIdx.x, w = tid>>5, l = tid&31;
    for (int t=tid; t<8192; t+=256) sv2x[t] = g_v2x[(size_t)b*8192 + t];
    if (tid<64)  sks[tid] = g_ksum[b*64 + tid];
    if (tid<128){ sg[tid] = lg[tid]; sb[tid] = lb[tid]; }
    __syncthreads();

    int nb0 = (blockIdx.x*8 + w)*8;
    float q0[8], q1[8];
    #pragma unroll
    for (int nd=0; nd<8; nd++){
        int n = nb0 + nd;
        if (n < NN){
            size_t i = (size_t)b*NN + n;
            q0[nd] = g_q[i*64 + l];
            q1[nd] = g_q[i*64 + 32 + l];
        } else { q0[nd] = 0.f; q1[nd] = 0.f; }
    }

    float4 acc[8]; float o2[8];
    #pragma unroll
    for (int nd=0; nd<8; nd++){ acc[nd]=make_float4(0.f,0.f,0.f,0.f); o2[nd]=0.f; }

    #pragma unroll 4
    for (int m=0; m<32; m++){
        float4 vx = ((float4*)(sv2x + m*128))[l];
        float km = sks[m];
        #pragma unroll
        for (int nd=0; nd<8; nd++){
            float qm = __shfl_sync(0xffffffffu, q0[nd], m);
            acc[nd].x = fmaf(qm, vx.x, acc[nd].x);
            acc[nd].y = fmaf(qm, vx.y, acc[nd].y);
            acc[nd].z = fmaf(qm, vx.z, acc[nd].z);
            acc[nd].w = fmaf(qm, vx.w, acc[nd].w);
            o2[nd]    = fmaf(qm, km, o2[nd]);
        }
    }
    #pragma unroll 4
    for (int m=0; m<32; m++){
        float4 vx = ((float4*)(sv2x + (m+32)*128))[l];
        float km = sks[m+32];
        #pragma unroll
        for (int nd=0; nd<8; nd++){
            float qm = __shfl_sync(0xffffffffu, q1[nd], m);
            acc[nd].x = fmaf(qm, vx.x, acc[nd].x);
            acc[nd].y = fmaf(qm, vx.y, acc[nd].y);
            acc[nd].z = fmaf(qm, vx.z, acc[nd].z);
            acc[nd].w = fmaf(qm, vx.w, acc[nd].w);
            o2[nd]    = fmaf(qm, km, o2[nd]);
        }
    }

    float4 g4 = ((float4*)sg)[l];
    float4 b4 = ((float4*)sb)[l];
    #pragma unroll 1
    for (int nd=0; nd<8; nd++){
        int n = nb0 + nd;
        if (n >= NN) continue;
        size_t i = (size_t)b*NN + n;
        float inv = 1.f / o2[nd];
        float4 res = ((const float4*)res_in)[i*32 + l];
        float4 t;
        t.x = fmaf(acc[nd].x, inv, res.x);
        t.y = fmaf(acc[nd].y, inv, res.y);
        t.z = fmaf(acc[nd].z, inv, res.z);
        t.w = fmaf(acc[nd].w, inv, res.w);
        float mu = warpSum(t.x+t.y+t.z+t.w) * (1.f/128.f);
        float dx=t.x-mu, dy=t.y-mu, dz=t.z-mu, dw=t.w-mu;
        float var = warpSum(dx*dx+dy*dy+dz*dz+dw*dw) * (1.f/128.f);
        float rs = rsqrtf(var + EPSLN);
        float4 o;
        o.x = dx*rs*g4.x + b4.x;
        o.y = dy*rs*g4.y + b4.y;
        o.z = dz*rs*g4.z + b4.z;
        o.w = dw*rs*g4.w + b4.w;
        ((float4*)g_h)[i*32 + l] = o;
    }
}

/* -------- relu(concat(h0,h)) @ W_reg.T + b_reg, transposed out ------- */
__global__ void final_k(const float* __restrict__ Wreg, const float* __restrict__ breg,
                        float* __restrict__ out)
{
    __shared__ float sWrT[256*12];
    __shared__ float sbr[12];
    int tid = threadIdx.x;
    for (int t=tid; t<3072; t+=256){ int to=t>>8, j=t&255; sWrT[j*12+to] = Wreg[t]; }
    if (tid<12) sbr[tid] = breg[tid];
    __syncthreads();

    int w = tid>>5, l = tid&31;
    int i = blockIdx.x*8 + w;
    int b = i / NN;
    int n = i - b*NN;
    size_t hb = (size_t)i*128;

    float acc[12];
    #pragma unroll
    for (int t=0;t<12;t++) acc[t]=0.f;

    #pragma unroll
    for (int c=0;c<8;c++){
        int j = c*32 + l;
        float vIn = (j < 128) ? g_h0[hb + j] : g_h[hb + j - 128];
        vIn = fmaxf(vIn, 0.f);
        #pragma unroll
        for (int t=0;t<12;t++) acc[t] = fmaf(vIn, sWrT[j*12+t], acc[t]);
    }
    #pragma unroll
    for (int t=0;t<12;t++) acc[t] = warpSum(acc[t]);
    if (l < 12) out[((size_t)b*12 + l)*NN + n] = acc[l] + sbr[l];
}

/* ------------------------------ launch ------------------------------- */
extern "C" void kernel_launch(void* const* d_in, const int* in_sizes, int n_in,
                              void* d_out, int out_size)
{
    const float* x        = (const float*)d_in[0];
    const float* node_emb = (const float*)d_in[1];
    const float* time_emb = (const float*)d_in[2];
    const float* week_emb = (const float*)d_in[3];
    const float* Win      = (const float*)d_in[4];
    const float* bin      = (const float*)d_in[5];
    const float* W1       = (const float*)d_in[6];
    const float* b1       = (const float*)d_in[7];
    const float* W2       = (const float*)d_in[8];
    const float* b2       = (const float*)d_in[9];
    const float* Wreg     = (const float*)d_in[10];
    const float* breg     = (const float*)d_in[11];
    const float* proj     = (const float*)d_in[12];

    cudaFuncSetAttribute(glu3_k, cudaFuncAttributeMaxDynamicSharedMemorySize, G3_TOT);

    float* g_h_ptr;  cudaGetSymbolAddress((void**)&g_h_ptr,  g_h);
    float* g_h0_ptr; cudaGetSymbolAddress((void**)&g_h0_ptr, g_h0);

    initmx_k<<<1,32>>>();
    phase1_k<<<NT/64,256>>>(x, node_emb, time_emb, week_emb,
                            Win, bin, W1, b1, W2, b2, proj);
    computek_k<<<(NT*64)/256,256>>>();
    ksump_k<<<dim3(CH,NB),256>>>();
    ksumr_k<<<1,256>>>();

    for (int layer=0; layer<2; layer++){
        const float* wi = (const float*)d_in[13 + layer*6 + 0];
        const float* bi = (const float*)d_in[13 + layer*6 + 1];
        const float* wo = (const float*)d_in[13 + layer*6 + 2];
        const float* bo = (const float*)d_in[13 + layer*6 + 3];
        const float* lg = (const float*)d_in[13 + layer*6 + 4];
        const float* lb = (const float*)d_in[13 + layer*6 + 5];

        const float* hin = (layer == 0) ? g_h0_ptr : g_h_ptr;

        glu3_k<<<148,512,G3_TOT>>>(hin, wi, bi, wo, bo);
        kvredmma_k<<<dim3(CH,NB),256>>>();
        vred_k<<<128,256>>>();
        attn_k<<<dim3((NN+63)/64,NB),256>>>(hin, lg, lb);
    }

    final_k<<<NT/8,256>>>(Wreg, breg, (float*)d_out);
}

// round 9
// speedup vs baseline: 1.1220x; 1.1220x over previous
#include <cuda_runtime.h>
#include <cuda_bf16.h>
#include <cuda_fp16.h>
#include <math.h>
#include <stdint.h>

#define NB 4
#define NN 50000
#define NT (NB*NN)
#define H4 128
#define RF 64
#define CH 98
#define CHSZ 512

#define ALPHA 0.4204482076268573f   /* 32^-0.25 */
#define RATIO 0.125f                /* 1/sqrt(64) */
#define EPSRF 1e-6f
#define EPSLN 1e-5f

/* ------------------------------ scratch ------------------------------ */
__device__ float  g_h0[(size_t)NT*H4];
__device__ float  g_h [(size_t)NT*H4];
__device__ __half g_vh[(size_t)NT*H4];
__device__ float  g_q [(size_t)NT*RF];
__device__ float  g_dash2[(size_t)NT*RF];
__device__ float  g_diag2[NT];
__device__ __half g_kh[(size_t)NT*RF];
__device__ int    g_mx[NB];
__device__ float  g_part [(size_t)NB*CH*RF*H4];
__device__ float  g_kpart[(size_t)NB*CH*RF];
__device__ float  g_v2x[(size_t)NB*RF*H4];
__device__ float  g_ksum[NB*RF];
/* precomputed LUTs: a = A-luts summed; dash = D-luts summed */
__device__ float  g_a1n[(size_t)NN*32], g_a2n[(size_t)NN*32];
__device__ float  g_d1n[(size_t)NN*64], g_d2n[(size_t)NN*64];
__device__ float  g_a1t[288*32], g_a2t[288*32];
__device__ float  g_d1t[288*64], g_d2t[288*64];
__device__ float  g_a1w[7*32],  g_a2w[7*32];
__device__ float  g_d1w[7*64],  g_d2w[7*64];
__device__ float  g_a1b[32],    g_a2b[32];
__device__ float  g_d1b[64],    g_d2b[64];

/* ------------------------------ helpers ------------------------------ */
__device__ __forceinline__ float warpSum(float v){
    #pragma unroll
    for (int o=16;o;o>>=1) v += __shfl_xor_sync(0xffffffffu, v, o);
    return v;
}
__device__ __forceinline__ float warpMax(float v){
    #pragma unroll
    for (int o=16;o;o>>=1) v = fmaxf(v, __shfl_xor_sync(0xffffffffu, v, o));
    return v;
}
__device__ __forceinline__ int f2ord(float f){
    int i = __float_as_int(f);
    return (i >= 0) ? i : (i ^ 0x7FFFFFFF);
}
__device__ __forceinline__ float ord2f(int i){
    return __int_as_float((i >= 0) ? i : (i ^ 0x7FFFFFFF));
}

/* --------------------- mma.sync helpers (base sm_100 ISA) ------------ */
__device__ __forceinline__ uint32_t smem_u32(const void* p){
    uint32_t a;
    asm("{ .reg .u64 t; cvta.to.shared.u64 t, %1; cvt.u32.u64 %0, t; }"
        : "=r"(a) : "l"(p));
    return a;
}
__device__ __forceinline__ void ldsm_x4(uint32_t* r, uint32_t addr){
    asm volatile("ldmatrix.sync.aligned.m8n8.x4.shared.b16 {%0,%1,%2,%3}, [%4];"
        : "=r"(r[0]), "=r"(r[1]), "=r"(r[2]), "=r"(r[3]) : "r"(addr));
}
__device__ __forceinline__ void mma16816h(float* d, const uint32_t* a, const uint32_t* b){
    asm volatile("mma.sync.aligned.m16n8k16.row.col.f32.f16.f16.f32 "
        "{%0,%1,%2,%3}, {%4,%5,%6,%7}, {%8,%9}, {%0,%1,%2,%3};"
        : "+f"(d[0]), "+f"(d[1]), "+f"(d[2]), "+f"(d[3])
        : "r"(a[0]), "r"(a[1]), "r"(a[2]), "r"(a[3]), "r"(b[0]), "r"(b[1]));
}
__device__ __forceinline__ uint4 pack8_f16(const float* src){
    float4 a = ((const float4*)src)[0];
    float4 b = ((const float4*)src)[1];
    __half2 p0 = __floats2half2_rn(a.x, a.y);
    __half2 p1 = __floats2half2_rn(a.z, a.w);
    __half2 p2 = __floats2half2_rn(b.x, b.y);
    __half2 p3 = __floats2half2_rn(b.z, b.w);
    uint4 w;
    w.x = *reinterpret_cast<uint32_t*>(&p0);
    w.y = *reinterpret_cast<uint32_t*>(&p1);
    w.z = *reinterpret_cast<uint32_t*>(&p2);
    w.w = *reinterpret_cast<uint32_t*>(&p3);
    return w;
}

/* ------------------------------ init --------------------------------- */
__global__ void initmx_k(){
    if (threadIdx.x < NB) g_mx[threadIdx.x] = (int)0x80000000;
}

/* ------------- LUT precompute: time/week/bias (296 entries) ---------- */
__global__ void pre_small_k(const float* __restrict__ time_emb,
                            const float* __restrict__ week_emb,
                            const float* __restrict__ W1, const float* __restrict__ b1,
                            const float* __restrict__ W2, const float* __restrict__ b2,
                            const float* __restrict__ proj)
{
    __shared__ float sT1[32*32], sU1[32*32], sT2[32*32], sU2[32*32]; /* [d][h] */
    __shared__ float sprojT[32*64];
    __shared__ float sv[8][32], snv[8][32];
    int tid = threadIdx.x;
    for (int t=tid; t<1024; t+=256){
        int h=t>>5, d=t&31;
        sT1[d*32+h] = W1[h*96 + 32 + d];
        sU1[d*32+h] = W1[h*96 + 64 + d];
        sT2[d*32+h] = W2[h*96 + 32 + d];
        sU2[d*32+h] = W2[h*96 + 64 + d];
    }
    for (int t=tid; t<2048; t+=256){ int m=t>>5, d=t&31; sprojT[d*64+m] = proj[m*32+d]; }
    __syncthreads();

    int w = tid>>5, l = tid&31;
    int e = blockIdx.x*8 + w;
    if (e >= 296) return;

    float a1, a2;
    float *A1, *A2, *D1, *D2;
    if (e < 288){
        sv[w][l] = time_emb[e*32 + l]; __syncwarp();
        a1 = 0.f; a2 = 0.f;
        #pragma unroll
        for (int d=0; d<32; d++){
            float v = sv[w][d];
            a1 = fmaf(sT1[d*32+l], v, a1);
            a2 = fmaf(sT2[d*32+l], v, a2);
        }
        A1 = g_a1t + e*32; A2 = g_a2t + e*32;
        D1 = g_d1t + e*64; D2 = g_d2t + e*64;
    } else if (e < 295){
        int k = e - 288;
        sv[w][l] = week_emb[k*32 + l]; __syncwarp();
        a1 = 0.f; a2 = 0.f;
        #pragma unroll
        for (int d=0; d<32; d++){
            float v = sv[w][d];
            a1 = fmaf(sU1[d*32+l], v, a1);
            a2 = fmaf(sU2[d*32+l], v, a2);
        }
        A1 = g_a1w + k*32; A2 = g_a2w + k*32;
        D1 = g_d1w + k*64; D2 = g_d2w + k*64;
    } else {
        a1 = b1[l]; a2 = b2[l];
        A1 = g_a1b; A2 = g_a2b; D1 = g_d1b; D2 = g_d2b;
    }
    a1 *= ALPHA; a2 *= ALPHA;
    A1[l] = a1; A2[l] = a2;

    snv[w][l] = a1; __syncwarp();
    float d0=0.f, d1=0.f;
    #pragma unroll
    for (int dd=0; dd<32; dd++){
        float f = snv[w][dd];
        d0 = fmaf(f, sprojT[dd*64+l],    d0);
        d1 = fmaf(f, sprojT[dd*64+32+l], d1);
    }
    D1[l] = d0; D1[32+l] = d1;
    __syncwarp();
    snv[w][l] = a2; __syncwarp();
    d0=0.f; d1=0.f;
    #pragma unroll
    for (int dd=0; dd<32; dd++){
        float f = snv[w][dd];
        d0 = fmaf(f, sprojT[dd*64+l],    d0);
        d1 = fmaf(f, sprojT[dd*64+32+l], d1);
    }
    D2[l] = d0; D2[32+l] = d1;
}

/* ------------- LUT precompute: per-node (50000 entries) -------------- */
__global__ void pre_node_k(const float* __restrict__ node_emb,
                           const float* __restrict__ W1, const float* __restrict__ W2,
                           const float* __restrict__ proj)
{
    __shared__ float sW1T[32*32], sW2T[32*32];   /* [d][h] (node cols 0..31) */
    __shared__ float sprojT[32*64];
    __shared__ float sne[8][32], snv[8][32];
    int tid = threadIdx.x;
    for (int t=tid; t<1024; t+=256){
        int h=t>>5, d=t&31;
        sW1T[d*32+h] = W1[h*96 + d];
        sW2T[d*32+h] = W2[h*96 + d];
    }
    for (int t=tid; t<2048; t+=256){ int m=t>>5, d=t&31; sprojT[d*64+m] = proj[m*32+d]; }
    __syncthreads();

    int w = tid>>5, l = tid&31;
    int n = blockIdx.x*8 + w;           /* grid = NN/8 = 6250 exact */

    sne[w][l] = node_emb[n*32 + l]; __syncwarp();
    float a1 = 0.f, a2 = 0.f;
    #pragma unroll
    for (int d=0; d<32; d++){
        float v = sne[w][d];
        a1 = fmaf(sW1T[d*32+l], v, a1);
        a2 = fmaf(sW2T[d*32+l], v, a2);
    }
    a1 *= ALPHA; a2 *= ALPHA;
    g_a1n[(size_t)n*32 + l] = a1;
    g_a2n[(size_t)n*32 + l] = a2;

    snv[w][l] = a1; __syncwarp();
    float d0=0.f, d1=0.f;
    #pragma unroll
    for (int dd=0; dd<32; dd++){
        float f = snv[w][dd];
        d0 = fmaf(f, sprojT[dd*64+l],    d0);
        d1 = fmaf(f, sprojT[dd*64+32+l], d1);
    }
    g_d1n[(size_t)n*64 + l] = d0;
    g_d1n[(size_t)n*64 + 32 + l] = d1;
    __syncwarp();
    snv[w][l] = a2; __syncwarp();
    d0=0.f; d1=0.f;
    #pragma unroll
    for (int dd=0; dd<32; dd++){
        float f = snv[w][dd];
        d0 = fmaf(f, sprojT[dd*64+l],    d0);
        d1 = fmaf(f, sprojT[dd*64+32+l], d1);
    }
    g_d2n[(size_t)n*64 + l] = d0;
    g_d2n[(size_t)n*64 + 32 + l] = d1;
}

/* --------------------------- phase 1 (LUT-based) --------------------- */
__global__ void phase1_k(const float* __restrict__ x,
                         const float* __restrict__ node_emb,
                         const float* __restrict__ time_emb,
                         const float* __restrict__ week_emb,
                         const float* __restrict__ Win, const float* __restrict__ bin)
{
    __shared__ float sWinT[36*32];
    __shared__ float sbin[32];
    __shared__ float sxv[8][40];
    __shared__ int   sbmax[NB];

    int tid = threadIdx.x;
    for (int t=tid; t<32*36; t+=256){ int h=t/36, j=t%36; sWinT[j*32+h]=Win[t]; }
    if (tid<32) sbin[tid]=bin[tid];
    if (tid<NB) sbmax[tid] = (int)0x80000000;
    __syncthreads();

    int w = tid>>5, l = tid&31;
    int i = blockIdx.x*8 + w;           /* grid = NT/8 = 25000, no straddle (NN%8==0) */
    int b = i / NN;
    int n = i - b*NN;

    const float* xr = x + (size_t)i*36;
    sxv[w][l] = xr[l];
    if (l < 4) sxv[w][32+l] = xr[32+l];
    __syncwarp();

    int ti = (int)(sxv[w][34]*288.0f); ti = min(max(ti,0),287);
    int wk = (int)(sxv[w][35]);        wk = min(max(wk,0),6);

    float ne = node_emb[n*32+l];
    float te = time_emb[ti*32+l];
    float we = week_emb[wk*32+l];

    float inp = sbin[l];
    #pragma unroll
    for (int j=0;j<36;j++) inp = fmaf(sWinT[j*32+l], sxv[w][j], inp);

    size_t hb = (size_t)i*128;
    g_h0[hb+l]=inp; g_h0[hb+32+l]=ne; g_h0[hb+64+l]=te; g_h0[hb+96+l]=we;

    /* ---- map 1 (q) ---- */
    float a1 = g_a1n[(size_t)n*32+l] + g_a1t[ti*32+l] + g_a1w[wk*32+l] + g_a1b[l];
    float diag1 = 0.5f * warpSum(a1*a1);
    float d0 = g_d1n[(size_t)n*64+l]    + g_d1t[ti*64+l]    + g_d1w[wk*64+l]    + g_d1b[l];
    float d1 = g_d1n[(size_t)n*64+32+l] + g_d1t[ti*64+32+l] + g_d1w[wk*64+32+l] + g_d1b[32+l];
    float mx1 = warpMax(fmaxf(d0,d1));
    g_q[(size_t)i*64 + l]      = RATIO*(expf(d0 - diag1 - mx1) + EPSRF);
    g_q[(size_t)i*64 + 32 + l] = RATIO*(expf(d1 - diag1 - mx1) + EPSRF);

    /* ---- map 2 (k: needs batch-global max) ---- */
    float a2 = g_a2n[(size_t)n*32+l] + g_a2t[ti*32+l] + g_a2w[wk*32+l] + g_a2b[l];
    float diag2 = 0.5f * warpSum(a2*a2);
    d0 = g_d2n[(size_t)n*64+l]    + g_d2t[ti*64+l]    + g_d2w[wk*64+l]    + g_d2b[l];
    d1 = g_d2n[(size_t)n*64+32+l] + g_d2t[ti*64+32+l] + g_d2w[wk*64+32+l] + g_d2b[32+l];
    g_dash2[(size_t)i*64 + l]      = d0;
    g_dash2[(size_t)i*64 + 32 + l] = d1;
    if (l==0) g_diag2[i] = diag2;
    float mx2 = warpMax(fmaxf(d0,d1));
    if (l==0) atomicMax(&sbmax[b], f2ord(mx2));

    __syncthreads();
    if (tid < NB && sbmax[tid] != (int)0x80000000)
        atomicMax(&g_mx[tid], sbmax[tid]);
}

/* --------------------------- k features (fp16 out) ------------------- */
__global__ void computek_k(){
    int idx = blockIdx.x*256 + threadIdx.x;
    int i = idx >> 6;
    int b = i / NN;
    float mx = ord2f(g_mx[b]);
    float val = RATIO*(expf(g_dash2[idx] - g_diag2[i] - mx) + EPSRF);
    g_kh[idx] = __float2half(val);
}

/* ------------------- ksum partial + final (hoisted) ------------------ */
__global__ void ksump_k(){
    __shared__ float red[4][64];
    int b = blockIdx.y, ch = blockIdx.x;
    int tid = threadIdx.x;
    int m = tid & 63, part = tid >> 6;
    float s = 0.f;
    int nb = ch*CHSZ + part*128;
    #pragma unroll 4
    for (int nn=0; nn<128; nn++){
        int n = nb + nn;
        if (n < NN) s += __half2float(g_kh[((size_t)(b*NN+n))*64 + m]);
    }
    red[part][m] = s;
    __syncthreads();
    if (part == 0){
        float t = red[0][m] + red[1][m] + red[2][m] + red[3][m];
        g_kpart[(size_t)(b*CH+ch)*64 + m] = t;
    }
}

__global__ void ksumr_k(){
    int tid = threadIdx.x;
    int b = tid >> 6, m = tid & 63;
    float s = 0.f;
    for (int ch=0; ch<CH; ch++)
        s += g_kpart[(size_t)(b*CH+ch)*64 + m];
    g_ksum[b*64 + m] = s;
}

/* ------------------------- GLU via mma.sync (fp16) ------------------- */
#define GT_TILES ((NT + 255)/256)
#define G3_SA   0
#define G3_SB   65536
#define G3_SBI  131072
#define G3_SBO  131584
#define G3_TOT  132096

extern __shared__ char gsm2[];

__global__ void __launch_bounds__(512,1)
glu3_k(const float* __restrict__ hin,
       const float* __restrict__ wi, const float* __restrict__ bi,
       const float* __restrict__ wo, const float* __restrict__ bo)
{
    char* SA = gsm2 + G3_SA;
    char* SB = gsm2 + G3_SB;
    float* sbi = (float*)(gsm2 + G3_SBI);
    float* sbo = (float*)(gsm2 + G3_SBO);
    int tid = threadIdx.x;

    for (int c = tid; c < 4096; c += 512){
        int n = c >> 4, ch = c & 15;
        const float* src = (n < 128) ? (wi + (size_t)n*128 + ch*8)
                                     : (wo + (size_t)(n-128)*128 + ch*8);
        *reinterpret_cast<uint4*>(SB + n*256 + ((ch ^ (n&7))<<4)) = pack8_f16(src);
    }
    if (tid < 128){ sbi[tid] = bi[tid]; sbo[tid] = bo[tid]; }

    int w = tid>>5, l = tid&31;
    uint32_t saB = smem_u32(SA);
    uint32_t sbB = smem_u32(SB);

    int a_row = (w<<4) + (l & 15);
    int er    = (w<<4) + (l>>2);

    for (int tile = blockIdx.x; tile < GT_TILES; tile += gridDim.x){
        int base = tile << 8;

        for (int c = tid; c < 4096; c += 512){
            int r = c >> 4, ch = c & 15;
            uint4 pw = make_uint4(0,0,0,0);
            if (base + r < NT)
                pw = pack8_f16(hin + (size_t)(base + r)*128 + ch*8);
            *reinterpret_cast<uint4*>(SA + r*256 + ((ch ^ (r&7))<<4)) = pw;
        }
        __syncthreads();

        uint32_t Af[8][4];
        #pragma unroll
        for (int ks=0; ks<8; ks++){
            int kc = (ks<<1) + (l>>4);
            ldsm_x4(Af[ks], saB + a_row*256 + ((kc ^ (a_row&7))<<4));
        }

        #pragma unroll 1
        for (int nb=0; nb<16; nb++){
            int nrI = (nb<<3) + (l&7);
            int nrO = nrI + 128;
            uint32_t BI[16], BO[16];
            #pragma unroll
            for (int j=0;j<4;j++){
                int kc = (j<<2) + (l>>3);
                ldsm_x4(&BI[j<<2], sbB + nrI*256 + ((kc ^ (nrI&7))<<4));
                ldsm_x4(&BO[j<<2], sbB + nrO*256 + ((kc ^ (nrO&7))<<4));
            }
            float dI[4] = {0.f,0.f,0.f,0.f};
            float dO[4] = {0.f,0.f,0.f,0.f};
            #pragma unroll
            for (int ks=0; ks<8; ks++){
                mma16816h(dI, Af[ks], &BI[ks<<1]);
                mma16816h(dO, Af[ks], &BO[ks<<1]);
            }

            int c0 = (nb<<3) + ((l&3)<<1);
            float bi0 = sbi[c0], bi1 = sbi[c0+1];
            float bo0 = sbo[c0], bo1 = sbo[c0+1];
            int n0 = base + er;
            int n1 = n0 + 8;
            if (n0 < NT){
                float aI0 = dI[0] + bi0, aI1 = dI[1] + bi1;
                float ox = (dO[0] + bo0) / (1.f + expf(-aI0));
                float oy = (dO[1] + bo1) / (1.f + expf(-aI1));
                *reinterpret_cast<__half2*>(g_vh + (size_t)n0*128 + c0) = __floats2half2_rn(ox, oy);
            }
            if (n1 < NT){
                float aI2 = dI[2] + bi0, aI3 = dI[3] + bi1;
                float ox = (dO[2] + bo0) / (1.f + expf(-aI2));
                float oy = (dO[3] + bo1) / (1.f + expf(-aI3));
                *reinterpret_cast<__half2*>(g_vh + (size_t)n1*128 + c0) = __floats2half2_rn(ox, oy);
            }
        }
        __syncthreads();
    }
}

/* --------------- K^T V partials via mma.sync (deterministic) --------- */
#define KT_PAD 40
__global__ void __launch_bounds__(256,1)
kvredmma_k(){
    __shared__ __align__(16) __half SKt[64*KT_PAD];
    __shared__ __align__(16) __half SVt[128*KT_PAD];
    int b = blockIdx.y, ch = blockIdx.x;
    int tid = threadIdx.x, w = tid>>5, l = tid&31;
    uint32_t skB = smem_u32(SKt), svB = smem_u32(SVt);

    float acc[4][2][4];
    #pragma unroll
    for (int mt=0;mt<4;mt++)
        #pragma unroll
        for (int nb=0;nb<2;nb++)
            #pragma unroll
            for (int r=0;r<4;r++) acc[mt][nb][r] = 0.f;

    int nb0 = ch*CHSZ;
    #pragma unroll 1
    for (int c0=0; c0<CHSZ; c0+=32){
        int nbase = nb0 + c0;
        {
            int node = tid & 31, rg = tid >> 5;
            int n = nbase + node;
            if (n < NN){
                const __half2* s2 = (const __half2*)(g_kh + ((size_t)(b*NN+n))*64 + rg*8);
                #pragma unroll
                for (int j=0;j<4;j++){
                    __half2 p = s2[j];
                    SKt[(rg*8 + 2*j  )*KT_PAD + node] = __low2half(p);
                    SKt[(rg*8 + 2*j+1)*KT_PAD + node] = __high2half(p);
                }
            } else {
                #pragma unroll
                for (int j=0;j<4;j++){
                    SKt[(rg*8 + 2*j  )*KT_PAD + node] = __float2half(0.f);
                    SKt[(rg*8 + 2*j+1)*KT_PAD + node] = __float2half(0.f);
                }
            }
        }
        {
            int node = tid & 31, hg = tid >> 5;
            int n = nbase + node;
            if (n < NN){
                const __half2* s2 = (const __half2*)(g_vh + ((size_t)(b*NN+n))*128 + hg*16);
                #pragma unroll
                for (int j=0;j<8;j++){
                    __half2 p = s2[j];
                    SVt[(hg*16 + 2*j  )*KT_PAD + node] = __low2half(p);
                    SVt[(hg*16 + 2*j+1)*KT_PAD + node] = __high2half(p);
                }
            } else {
                #pragma unroll
                for (int j=0;j<8;j++){
                    SVt[(hg*16 + 2*j  )*KT_PAD + node] = __float2half(0.f);
                    SVt[(hg*16 + 2*j+1)*KT_PAD + node] = __float2half(0.f);
                }
            }
        }
        __syncthreads();

        uint32_t Bv[2][4];
        #pragma unroll
        for (int nb=0;nb<2;nb++){
            int row = w*16 + nb*8 + (l&7);
            ldsm_x4(Bv[nb], svB + row*(KT_PAD*2) + ((l>>3)<<4));
        }
        #pragma unroll
        for (int ks=0; ks<2; ks++){
            uint32_t Af[4][4];
            #pragma unroll
            for (int mt=0;mt<4;mt++){
                int row = mt*16 + (l&15);
                ldsm_x4(Af[mt], skB + row*(KT_PAD*2) + (((ks<<1) + (l>>4))<<4));
            }
            #pragma unroll
            for (int mt=0;mt<4;mt++){
                mma16816h(acc[mt][0], Af[mt], &Bv[0][ks<<1]);
                mma16816h(acc[mt][1], Af[mt], &Bv[1][ks<<1]);
            }
        }
        __syncthreads();
    }

    size_t pb = (size_t)(b*CH+ch);
    #pragma unroll
    for (int mt=0;mt<4;mt++){
        #pragma unroll
        for (int nb=0;nb<2;nb++){
            int rf0 = mt*16 + (l>>2);
            int hd = w*16 + nb*8 + 2*(l&3);
            float2 v0 = make_float2(acc[mt][nb][0], acc[mt][nb][1]);
            float2 v1 = make_float2(acc[mt][nb][2], acc[mt][nb][3]);
            *reinterpret_cast<float2*>(&g_part[(pb*64 + rf0    )*128 + hd]) = v0;
            *reinterpret_cast<float2*>(&g_part[(pb*64 + rf0 + 8)*128 + hd]) = v1;
        }
    }
}

__global__ void vred_k(){
    int idx = blockIdx.x*256 + threadIdx.x;
    int b = idx >> 13;
    int rem = idx & 8191;
    int m = rem >> 7, d = rem & 127;
    float s = 0.f;
    for (int ch=0; ch<CH; ch++)
        s += g_part[((size_t)(b*CH+ch)*64 + m)*128 + d];
    g_v2x[((size_t)b*64 + m)*128 + d] = s;
}

/* ------------- attention out + residual + layernorm ------------------ */
__global__ void attn_k(const float* __restrict__ res_in,
                       const float* __restrict__ lg, const float* __restrict__ lb){
    __shared__ float sv2x[64*128];
    __shared__ float sks[64];
    __shared__ float sg[128], sb[128];

    int b = blockIdx.y;
    int tid = threadIdx.x, w = tid>>5, l = tid&31;
    for (int t=tid; t<8192; t+=256) sv2x[t] = g_v2x[(size_t)b*8192 + t];
    if (tid<64)  sks[tid] = g_ksum[b*64 + tid];
    if (tid<128){ sg[tid] = lg[tid]; sb[tid] = lb[tid]; }
    __syncthreads();

    int nb0 = (blockIdx.x*8 + w)*8;
    float q0[8], q1[8];
    #pragma unroll
    for (int nd=0; nd<8; nd++){
        int n = nb0 + nd;
        if (n < NN){
            size_t i = (size_t)b*NN + n;
            q0[nd] = g_q[i*64 + l];
            q1[nd] = g_q[i*64 + 32 + l];
        } else { q0[nd] = 0.f; q1[nd] = 0.f; }
    }

    float4 acc[8]; float o2[8];
    #pragma unroll
    for (int nd=0; nd<8; nd++){ acc[nd]=make_float4(0.f,0.f,0.f,0.f); o2[nd]=0.f; }

    #pragma unroll 4
    for (int m=0; m<32; m++){
        float4 vx = ((float4*)(sv2x + m*128))[l];
        float km = sks[m];
        #pragma unroll
        for (int nd=0; nd<8; nd++){
            float qm = __shfl_sync(0xffffffffu, q0[nd], m);
            acc[nd].x = fmaf(qm, vx.x, acc[nd].x);
            acc[nd].y = fmaf(qm, vx.y, acc[nd].y);
            acc[nd].z = fmaf(qm, vx.z, acc[nd].z);
            acc[nd].w = fmaf(qm, vx.w, acc[nd].w);
            o2[nd]    = fmaf(qm, km, o2[nd]);
        }
    }
    #pragma unroll 4
    for (int m=0; m<32; m++){
        float4 vx = ((float4*)(sv2x + (m+32)*128))[l];
        float km = sks[m+32];
        #pragma unroll
        for (int nd=0; nd<8; nd++){
            float qm = __shfl_sync(0xffffffffu, q1[nd], m);
            acc[nd].x = fmaf(qm, vx.x, acc[nd].x);
            acc[nd].y = fmaf(qm, vx.y, acc[nd].y);
            acc[nd].z = fmaf(qm, vx.z, acc[nd].z);
            acc[nd].w = fmaf(qm, vx.w, acc[nd].w);
            o2[nd]    = fmaf(qm, km, o2[nd]);
        }
    }

    float4 g4 = ((float4*)sg)[l];
    float4 b4 = ((float4*)sb)[l];
    #pragma unroll 1
    for (int nd=0; nd<8; nd++){
        int n = nb0 + nd;
        if (n >= NN) continue;
        size_t i = (size_t)b*NN + n;
        float inv = 1.f / o2[nd];
        float4 res = ((const float4*)res_in)[i*32 + l];
        float4 t;
        t.x = fmaf(acc[nd].x, inv, res.x);
        t.y = fmaf(acc[nd].y, inv, res.y);
        t.z = fmaf(acc[nd].z, inv, res.z);
        t.w = fmaf(acc[nd].w, inv, res.w);
        float mu = warpSum(t.x+t.y+t.z+t.w) * (1.f/128.f);
        float dx=t.x-mu, dy=t.y-mu, dz=t.z-mu, dw=t.w-mu;
        float var = warpSum(dx*dx+dy*dy+dz*dz+dw*dw) * (1.f/128.f);
        float rs = rsqrtf(var + EPSLN);
        float4 o;
        o.x = dx*rs*g4.x + b4.x;
        o.y = dy*rs*g4.y + b4.y;
        o.z = dz*rs*g4.z + b4.z;
        o.w = dw*rs*g4.w + b4.w;
        ((float4*)g_h)[i*32 + l] = o;
    }
}

/* -------- relu(concat(h0,h)) @ W_reg.T + b_reg, transposed out ------- */
__global__ void final_k(const float* __restrict__ Wreg, const float* __restrict__ breg,
                        float* __restrict__ out)
{
    __shared__ float sWrT[256*12];
    __shared__ float sbr[12];
    int tid = threadIdx.x;
    for (int t=tid; t<3072; t+=256){ int to=t>>8, j=t&255; sWrT[j*12+to] = Wreg[t]; }
    if (tid<12) sbr[tid] = breg[tid];
    __syncthreads();

    int w = tid>>5, l = tid&31;
    int i = blockIdx.x*8 + w;
    int b = i / NN;
    int n = i - b*NN;
    size_t hb = (size_t)i*128;

    float acc[12];
    #pragma unroll
    for (int t=0;t<12;t++) acc[t]=0.f;

    #pragma unroll
    for (int c=0;c<8;c++){
        int j = c*32 + l;
        float vIn = (j < 128) ? g_h0[hb + j] : g_h[hb + j - 128];
        vIn = fmaxf(vIn, 0.f);
        #pragma unroll
        for (int t=0;t<12;t++) acc[t] = fmaf(vIn, sWrT[j*12+t], acc[t]);
    }
    #pragma unroll
    for (int t=0;t<12;t++) acc[t] = warpSum(acc[t]);
    if (l < 12) out[((size_t)b*12 + l)*NN + n] = acc[l] + sbr[l];
}

/* ------------------------------ launch ------------------------------- */
extern "C" void kernel_launch(void* const* d_in, const int* in_sizes, int n_in,
                              void* d_out, int out_size)
{
    const float* x        = (const float*)d_in[0];
    const float* node_emb = (const float*)d_in[1];
    const float* time_emb = (const float*)d_in[2];
    const float* week_emb = (const float*)d_in[3];
    const float* Win      = (const float*)d_in[4];
    const float* bin      = (const float*)d_in[5];
    const float* W1       = (const float*)d_in[6];
    const float* b1       = (const float*)d_in[7];
    const float* W2       = (const float*)d_in[8];
    const float* b2       = (const float*)d_in[9];
    const float* Wreg     = (const float*)d_in[10];
    const float* breg     = (const float*)d_in[11];
    const float* proj     = (const float*)d_in[12];

    cudaFuncSetAttribute(glu3_k, cudaFuncAttributeMaxDynamicSharedMemorySize, G3_TOT);

    float* g_h_ptr;  cudaGetSymbolAddress((void**)&g_h_ptr,  g_h);
    float* g_h0_ptr; cudaGetSymbolAddress((void**)&g_h0_ptr, g_h0);

    initmx_k<<<1,32>>>();
    pre_small_k<<<37,256>>>(time_emb, week_emb, W1, b1, W2, b2, proj);
    pre_node_k<<<NN/8,256>>>(node_emb, W1, W2, proj);
    phase1_k<<<NT/8,256>>>(x, node_emb, time_emb, week_emb, Win, bin);
    computek_k<<<(NT*64)/256,256>>>();
    ksump_k<<<dim3(CH,NB),256>>>();
    ksumr_k<<<1,256>>>();

    for (int layer=0; layer<2; layer++){
        const float* wi = (const float*)d_in[13 + layer*6 + 0];
        const float* bi = (const float*)d_in[13 + layer*6 + 1];
        const float* wo = (const float*)d_in[13 + layer*6 + 2];
        const float* bo = (const float*)d_in[13 + layer*6 + 3];
        const float* lg = (const float*)d_in[13 + layer*6 + 4];
        const float* lb = (const float*)d_in[13 + layer*6 + 5];

        const float* hin = (layer == 0) ? g_h0_ptr : g_h_ptr;

        glu3_k<<<148,512,G3_TOT>>>(hin, wi, bi, wo, bo);
        kvredmma_k<<<dim3(CH,NB),256>>>();
        vred_k<<<128,256>>>();
        attn_k<<<dim3((NN+63)/64,NB),256>>>(hin, lg, lb);
    }

    final_k<<<NT/8,256>>>(Wreg, breg, (float*)d_out);
}